// round 1
// baseline (speedup 1.0000x reference)
#include <cuda_runtime.h>
#include <cuda_bf16.h>
#include <cstdint>

#define NITER   50
#define EPSF    0.1f
#define PCOEF   (1.0f/1.1f)
#define LOGHUGE 69.07755279f   /* log(1e30) */
#define NB      256
#define NN      256
#define KPAD    264            /* padded row length (bf16 elems): 528B stride, conflict-free */
#define DXC     (1.0f/256.0f)
#define DYC     (1.0f/256.0f)
#define PI2F    1.57079632679489662f

struct Smem {
    uint16_t K0[NN * KPAD];   // 135168 B, bf16 kernel matrix K0 = exp(-C/eps)
    float z[NN];              // exp(10*v_j)
    float w[NN];              // exp(10*u_i)
    float u[NN];
    float v[NN];
    float csave[NN];          // last col-pass sums (for col marginal)
    float part[16][NN];       // partial-sum scratch (16 KB)
    float red[16];
};

__device__ __forceinline__ float bflo(unsigned p) { return __uint_as_float(p << 16); }
__device__ __forceinline__ float bfhi(unsigned p) { return __uint_as_float(p & 0xFFFF0000u); }

__device__ __forceinline__ unsigned pack_bf16(float a, float b) {
    __nv_bfloat162 h = __floats2bfloat162_rn(a, b);   // .x = a (low 16), .y = b (high 16)
    return *reinterpret_cast<unsigned*>(&h);
}

__global__ void __launch_bounds__(512, 1)
wfr_kernel(const float* __restrict__ D, float* __restrict__ out)
{
    extern __shared__ char smraw[];
    Smem* sm = reinterpret_cast<Smem*>(smraw);
    const int b = blockIdx.x;
    const int t = threadIdx.x;
    const float* __restrict__ Db = D + (size_t)b * (NN * NN);

    // ---------------- Prologue: K0 = (cos(min(2D,pi/2)) + 1e-5)^20  (bf16, SMEM) ---------
    {
        const float4* __restrict__ D4 = reinterpret_cast<const float4*>(Db);
        #pragma unroll 4
        for (int k = 0; k < 32; k++) {
            int i4 = t + k * 512;
            float4 d = D4[i4];
            int e = i4 << 2;
            int i = e >> 8, j = e & (NN - 1);
            float c0 = __cosf(fminf(d.x * 2.0f, PI2F)) + 1e-5f;
            float c1 = __cosf(fminf(d.y * 2.0f, PI2F)) + 1e-5f;
            float c2 = __cosf(fminf(d.z * 2.0f, PI2F)) + 1e-5f;
            float c3 = __cosf(fminf(d.w * 2.0f, PI2F)) + 1e-5f;
            float k0 = exp2f(20.0f * __log2f(c0));
            float k1 = exp2f(20.0f * __log2f(c1));
            float k2 = exp2f(20.0f * __log2f(c2));
            float k3 = exp2f(20.0f * __log2f(c3));
            uint2 pk = make_uint2(pack_bf16(k0, k1), pack_bf16(k2, k3));
            *reinterpret_cast<uint2*>(&sm->K0[i * KPAD + j]) = pk;
        }
        if (t < NN) { sm->u[t] = 0.0f; sm->v[t] = 0.0f; sm->z[t] = 1.0f; }
    }
    __syncthreads();

    const int row  = t & (NN - 1);
    const int h    = t >> 8;        // j-half for row-style passes
    const int lane = t & 31;
    const int wp   = t >> 5;        // 16 warps
    const int j0   = lane << 3;     // 8 columns per thread in col pass
    const int ib   = wp << 4;       // 16 rows per warp in col pass

    // ---------------- 50 Sinkhorn iterations (eager rescale) ----------------
    for (int it = 0; it < NITER; it++) {
        // row pass: r_i = sum_j K0[i][j] * z[j]   (each thread: one row, half the columns)
        {
            const uint16_t* __restrict__ kr = sm->K0 + row * KPAD + h * 128;
            const float*    __restrict__ zh = sm->z + h * 128;
            float a0 = 0.f, a1 = 0.f, a2 = 0.f, a3 = 0.f;
            #pragma unroll
            for (int c = 0; c < 16; c++) {
                uint4  q  = *reinterpret_cast<const uint4*>(kr + c * 8);
                float4 z0 = *reinterpret_cast<const float4*>(zh + c * 8);
                float4 z1 = *reinterpret_cast<const float4*>(zh + c * 8 + 4);
                a0 = fmaf(bflo(q.x), z0.x, a0);
                a1 = fmaf(bfhi(q.x), z0.y, a1);
                a2 = fmaf(bflo(q.y), z0.z, a2);
                a3 = fmaf(bfhi(q.y), z0.w, a3);
                a0 = fmaf(bflo(q.z), z1.x, a0);
                a1 = fmaf(bfhi(q.z), z1.y, a1);
                a2 = fmaf(bflo(q.w), z1.z, a2);
                a3 = fmaf(bfhi(q.w), z1.w, a3);
            }
            sm->part[h][row] = (a0 + a1) + (a2 + a3);
        }
        __syncthreads();
        if (t < NN) {
            float r  = sm->part[0][t] + sm->part[1][t];
            float la = -PCOEF * (11.0f * sm->u[t] + __logf(DYC * r));
            la = fminf(la, LOGHUGE);                 // clip a at HUGE
            float un = sm->u[t] + EPSF * la;
            sm->u[t] = un;
            sm->w[t] = __expf(10.0f * un);
        }
        __syncthreads();

        // col pass: c_j = sum_i K0[i][j] * w[i]   (thread: 8 cols, 16 rows; warp covers all cols)
        {
            const uint16_t* __restrict__ kp = sm->K0 + ib * KPAD + j0;
            float c0 = 0.f, c1 = 0.f, c2 = 0.f, c3 = 0.f, c4 = 0.f, c5 = 0.f, c6 = 0.f, c7 = 0.f;
            #pragma unroll
            for (int ii = 0; ii < 16; ii++) {
                uint4 q = *reinterpret_cast<const uint4*>(kp + ii * KPAD);
                float wi = sm->w[ib + ii];
                c0 = fmaf(bflo(q.x), wi, c0);
                c1 = fmaf(bfhi(q.x), wi, c1);
                c2 = fmaf(bflo(q.y), wi, c2);
                c3 = fmaf(bfhi(q.y), wi, c3);
                c4 = fmaf(bflo(q.z), wi, c4);
                c5 = fmaf(bfhi(q.z), wi, c5);
                c6 = fmaf(bflo(q.w), wi, c6);
                c7 = fmaf(bfhi(q.w), wi, c7);
            }
            float4* pp = reinterpret_cast<float4*>(&sm->part[wp][j0]);
            pp[0] = make_float4(c0, c1, c2, c3);
            pp[1] = make_float4(c4, c5, c6, c7);
        }
        __syncthreads();
        if (t < NN) {
            float c = 0.0f;
            #pragma unroll
            for (int s = 0; s < 16; s++) c += sm->part[s][t];
            sm->csave[t] = c;
            float lb = -PCOEF * (11.0f * sm->v[t] + __logf(DXC * c));
            lb = fminf(lb, LOGHUGE);
            float vn = sm->v[t] + EPSF * lb;
            sm->v[t] = vn;
            sm->z[t] = __expf(10.0f * vn);
        }
        __syncthreads();
    }

    // ---------------- Epilogue: marginals + transport --------------------------------
    {
        const uint16_t* __restrict__ kr = sm->K0 + row * KPAD + h * 128;
        const float*    __restrict__ zh = sm->z + h * 128;
        const float*    __restrict__ dr = Db + row * NN + h * 128;
        float racc = 0.f, tacc = 0.f;
        #pragma unroll 4
        for (int c = 0; c < 16; c++) {
            uint4  q  = *reinterpret_cast<const uint4*>(kr + c * 8);
            float4 z0 = *reinterpret_cast<const float4*>(zh + c * 8);
            float4 z1 = *reinterpret_cast<const float4*>(zh + c * 8 + 4);
            float4 d0 = *reinterpret_cast<const float4*>(dr + c * 8);
            float4 d1 = *reinterpret_cast<const float4*>(dr + c * 8 + 4);

            float kz, cc, Cv;
            kz = bflo(q.x) * z0.x; racc += kz;
            cc = __cosf(fminf(d0.x * 2.0f, PI2F)) + 1e-5f; Cv = -2.0f * __logf(cc); tacc = fmaf(kz, Cv, tacc);
            kz = bfhi(q.x) * z0.y; racc += kz;
            cc = __cosf(fminf(d0.y * 2.0f, PI2F)) + 1e-5f; Cv = -2.0f * __logf(cc); tacc = fmaf(kz, Cv, tacc);
            kz = bflo(q.y) * z0.z; racc += kz;
            cc = __cosf(fminf(d0.z * 2.0f, PI2F)) + 1e-5f; Cv = -2.0f * __logf(cc); tacc = fmaf(kz, Cv, tacc);
            kz = bfhi(q.y) * z0.w; racc += kz;
            cc = __cosf(fminf(d0.w * 2.0f, PI2F)) + 1e-5f; Cv = -2.0f * __logf(cc); tacc = fmaf(kz, Cv, tacc);
            kz = bflo(q.z) * z1.x; racc += kz;
            cc = __cosf(fminf(d1.x * 2.0f, PI2F)) + 1e-5f; Cv = -2.0f * __logf(cc); tacc = fmaf(kz, Cv, tacc);
            kz = bfhi(q.z) * z1.y; racc += kz;
            cc = __cosf(fminf(d1.y * 2.0f, PI2F)) + 1e-5f; Cv = -2.0f * __logf(cc); tacc = fmaf(kz, Cv, tacc);
            kz = bflo(q.w) * z1.z; racc += kz;
            cc = __cosf(fminf(d1.z * 2.0f, PI2F)) + 1e-5f; Cv = -2.0f * __logf(cc); tacc = fmaf(kz, Cv, tacc);
            kz = bfhi(q.w) * z1.w; racc += kz;
            cc = __cosf(fminf(d1.w * 2.0f, PI2F)) + 1e-5f; Cv = -2.0f * __logf(cc); tacc = fmaf(kz, Cv, tacc);
        }
        sm->part[h][row]     = racc;
        sm->part[2 + h][row] = tacc;
    }
    __syncthreads();

    float val = 0.0f;
    if (t < NN) {
        float w_  = sm->w[t];
        float rm  = DYC * w_ * (sm->part[0][t] + sm->part[1][t]);
        float klr = rm * __logf(rm + 1e-10f) - rm + 1.0f;
        float tp  = w_ * (sm->part[2][t] + sm->part[3][t]) * (DXC * DYC);
        float cm  = DXC * sm->z[t] * sm->csave[t];
        float klc = cm * __logf(cm + 1e-10f) - cm + 1.0f;
        val = klr * DXC + klc * DYC + tp;
    }
    #pragma unroll
    for (int o = 16; o; o >>= 1) val += __shfl_down_sync(0xFFFFFFFFu, val, o);
    if (lane == 0) sm->red[wp] = val;
    __syncthreads();
    if (t == 0) {
        float s = 0.0f;
        #pragma unroll
        for (int i = 0; i < 16; i++) s += sm->red[i];
        out[b] = s;
    }
}

extern "C" void kernel_launch(void* const* d_in, const int* in_sizes, int n_in,
                              void* d_out, int out_size)
{
    const float* D = (const float*)d_in[0];
    float* out = (float*)d_out;
    (void)in_sizes; (void)n_in; (void)out_size;
    size_t smem = sizeof(Smem);
    cudaFuncSetAttribute(wfr_kernel, cudaFuncAttributeMaxDynamicSharedMemorySize, (int)smem);
    wfr_kernel<<<NB, 512, smem>>>(D, out);
}

// round 2
// speedup vs baseline: 1.0003x; 1.0003x over previous
#include <cuda_runtime.h>
#include <cuda_bf16.h>
#include <cstdint>

#define NITER   50
#define EPSF    0.1f
#define PCOEF   (1.0f/1.1f)
#define LOGHUGE 69.07755279f   /* log(1e30) */
#define NB      256
#define NN      256
#define KPAD    264            /* padded row length (bf16 elems): 528B stride, conflict-free */
#define DXC     (1.0f/256.0f)
#define DYC     (1.0f/256.0f)
#define PI2F    1.57079632679489662f

struct Smem {
    uint16_t K0[NN * KPAD];   // 135168 B, bf16 kernel matrix K0 = exp(-C/eps)
    float z[NN];              // exp(10*v_j)
    float w[NN];              // exp(10*u_i)
    float u[NN];
    float v[NN];
    float csave[NN];          // last col-pass sums (for col marginal)
    float part[16][NN];       // partial-sum scratch (16 KB)
    float red[16];
};

__device__ __forceinline__ float bflo(unsigned p) { return __uint_as_float(p << 16); }
__device__ __forceinline__ float bfhi(unsigned p) { return __uint_as_float(p & 0xFFFF0000u); }

__device__ __forceinline__ unsigned pack_bf16(float a, float b) {
    __nv_bfloat162 h = __floats2bfloat162_rn(a, b);   // .x = a (low 16), .y = b (high 16)
    return *reinterpret_cast<unsigned*>(&h);
}

__global__ void __launch_bounds__(512, 1)
wfr_kernel(const float* __restrict__ D, float* __restrict__ out)
{
    extern __shared__ char smraw[];
    Smem* sm = reinterpret_cast<Smem*>(smraw);
    const int b = blockIdx.x;
    const int t = threadIdx.x;
    const float* __restrict__ Db = D + (size_t)b * (NN * NN);

    // ---------------- Prologue: K0 = (cos(min(2D,pi/2)) + 1e-5)^20  (bf16, SMEM) ---------
    {
        const float4* __restrict__ D4 = reinterpret_cast<const float4*>(Db);
        #pragma unroll 4
        for (int k = 0; k < 32; k++) {
            int i4 = t + k * 512;
            float4 d = D4[i4];
            int e = i4 << 2;
            int i = e >> 8, j = e & (NN - 1);
            float c0 = __cosf(fminf(d.x * 2.0f, PI2F)) + 1e-5f;
            float c1 = __cosf(fminf(d.y * 2.0f, PI2F)) + 1e-5f;
            float c2 = __cosf(fminf(d.z * 2.0f, PI2F)) + 1e-5f;
            float c3 = __cosf(fminf(d.w * 2.0f, PI2F)) + 1e-5f;
            float k0 = exp2f(20.0f * __log2f(c0));
            float k1 = exp2f(20.0f * __log2f(c1));
            float k2 = exp2f(20.0f * __log2f(c2));
            float k3 = exp2f(20.0f * __log2f(c3));
            uint2 pk = make_uint2(pack_bf16(k0, k1), pack_bf16(k2, k3));
            *reinterpret_cast<uint2*>(&sm->K0[i * KPAD + j]) = pk;
        }
        if (t < NN) { sm->u[t] = 0.0f; sm->v[t] = 0.0f; sm->z[t] = 1.0f; }
    }
    __syncthreads();

    const int row  = t & (NN - 1);
    const int h    = t >> 8;        // j-half for row-style passes
    const int lane = t & 31;
    const int wp   = t >> 5;        // 16 warps
    const int j0   = lane << 3;     // 8 columns per thread in col pass
    const int ib   = wp << 4;       // 16 rows per warp in col pass

    // ---------------- 50 Sinkhorn iterations (eager rescale) ----------------
    for (int it = 0; it < NITER; it++) {
        // row pass: r_i = sum_j K0[i][j] * z[j]   (each thread: one row, half the columns)
        {
            const uint16_t* __restrict__ kr = sm->K0 + row * KPAD + h * 128;
            const float*    __restrict__ zh = sm->z + h * 128;
            float a0 = 0.f, a1 = 0.f, a2 = 0.f, a3 = 0.f;
            #pragma unroll
            for (int c = 0; c < 16; c++) {
                uint4  q  = *reinterpret_cast<const uint4*>(kr + c * 8);
                float4 z0 = *reinterpret_cast<const float4*>(zh + c * 8);
                float4 z1 = *reinterpret_cast<const float4*>(zh + c * 8 + 4);
                a0 = fmaf(bflo(q.x), z0.x, a0);
                a1 = fmaf(bfhi(q.x), z0.y, a1);
                a2 = fmaf(bflo(q.y), z0.z, a2);
                a3 = fmaf(bfhi(q.y), z0.w, a3);
                a0 = fmaf(bflo(q.z), z1.x, a0);
                a1 = fmaf(bfhi(q.z), z1.y, a1);
                a2 = fmaf(bflo(q.w), z1.z, a2);
                a3 = fmaf(bfhi(q.w), z1.w, a3);
            }
            sm->part[h][row] = (a0 + a1) + (a2 + a3);
        }
        __syncthreads();
        if (t < NN) {
            float r  = sm->part[0][t] + sm->part[1][t];
            float la = -PCOEF * (11.0f * sm->u[t] + __logf(DYC * r));
            la = fminf(la, LOGHUGE);                 // clip a at HUGE
            float un = sm->u[t] + EPSF * la;
            sm->u[t] = un;
            sm->w[t] = __expf(10.0f * un);
        }
        __syncthreads();

        // col pass: c_j = sum_i K0[i][j] * w[i]   (thread: 8 cols, 16 rows; warp covers all cols)
        {
            const uint16_t* __restrict__ kp = sm->K0 + ib * KPAD + j0;
            float c0 = 0.f, c1 = 0.f, c2 = 0.f, c3 = 0.f, c4 = 0.f, c5 = 0.f, c6 = 0.f, c7 = 0.f;
            #pragma unroll
            for (int ii = 0; ii < 16; ii++) {
                uint4 q = *reinterpret_cast<const uint4*>(kp + ii * KPAD);
                float wi = sm->w[ib + ii];
                c0 = fmaf(bflo(q.x), wi, c0);
                c1 = fmaf(bfhi(q.x), wi, c1);
                c2 = fmaf(bflo(q.y), wi, c2);
                c3 = fmaf(bfhi(q.y), wi, c3);
                c4 = fmaf(bflo(q.z), wi, c4);
                c5 = fmaf(bfhi(q.z), wi, c5);
                c6 = fmaf(bflo(q.w), wi, c6);
                c7 = fmaf(bfhi(q.w), wi, c7);
            }
            float4* pp = reinterpret_cast<float4*>(&sm->part[wp][j0]);
            pp[0] = make_float4(c0, c1, c2, c3);
            pp[1] = make_float4(c4, c5, c6, c7);
        }
        __syncthreads();
        if (t < NN) {
            float c = 0.0f;
            #pragma unroll
            for (int s = 0; s < 16; s++) c += sm->part[s][t];
            sm->csave[t] = c;
            float lb = -PCOEF * (11.0f * sm->v[t] + __logf(DXC * c));
            lb = fminf(lb, LOGHUGE);
            float vn = sm->v[t] + EPSF * lb;
            sm->v[t] = vn;
            sm->z[t] = __expf(10.0f * vn);
        }
        __syncthreads();
    }

    // ---------------- Epilogue: marginals + transport --------------------------------
    {
        const uint16_t* __restrict__ kr = sm->K0 + row * KPAD + h * 128;
        const float*    __restrict__ zh = sm->z + h * 128;
        const float*    __restrict__ dr = Db + row * NN + h * 128;
        float racc = 0.f, tacc = 0.f;
        #pragma unroll 4
        for (int c = 0; c < 16; c++) {
            uint4  q  = *reinterpret_cast<const uint4*>(kr + c * 8);
            float4 z0 = *reinterpret_cast<const float4*>(zh + c * 8);
            float4 z1 = *reinterpret_cast<const float4*>(zh + c * 8 + 4);
            float4 d0 = *reinterpret_cast<const float4*>(dr + c * 8);
            float4 d1 = *reinterpret_cast<const float4*>(dr + c * 8 + 4);

            float kz, cc, Cv;
            kz = bflo(q.x) * z0.x; racc += kz;
            cc = __cosf(fminf(d0.x * 2.0f, PI2F)) + 1e-5f; Cv = -2.0f * __logf(cc); tacc = fmaf(kz, Cv, tacc);
            kz = bfhi(q.x) * z0.y; racc += kz;
            cc = __cosf(fminf(d0.y * 2.0f, PI2F)) + 1e-5f; Cv = -2.0f * __logf(cc); tacc = fmaf(kz, Cv, tacc);
            kz = bflo(q.y) * z0.z; racc += kz;
            cc = __cosf(fminf(d0.z * 2.0f, PI2F)) + 1e-5f; Cv = -2.0f * __logf(cc); tacc = fmaf(kz, Cv, tacc);
            kz = bfhi(q.y) * z0.w; racc += kz;
            cc = __cosf(fminf(d0.w * 2.0f, PI2F)) + 1e-5f; Cv = -2.0f * __logf(cc); tacc = fmaf(kz, Cv, tacc);
            kz = bflo(q.z) * z1.x; racc += kz;
            cc = __cosf(fminf(d1.x * 2.0f, PI2F)) + 1e-5f; Cv = -2.0f * __logf(cc); tacc = fmaf(kz, Cv, tacc);
            kz = bfhi(q.z) * z1.y; racc += kz;
            cc = __cosf(fminf(d1.y * 2.0f, PI2F)) + 1e-5f; Cv = -2.0f * __logf(cc); tacc = fmaf(kz, Cv, tacc);
            kz = bflo(q.w) * z1.z; racc += kz;
            cc = __cosf(fminf(d1.z * 2.0f, PI2F)) + 1e-5f; Cv = -2.0f * __logf(cc); tacc = fmaf(kz, Cv, tacc);
            kz = bfhi(q.w) * z1.w; racc += kz;
            cc = __cosf(fminf(d1.w * 2.0f, PI2F)) + 1e-5f; Cv = -2.0f * __logf(cc); tacc = fmaf(kz, Cv, tacc);
        }
        sm->part[h][row]     = racc;
        sm->part[2 + h][row] = tacc;
    }
    __syncthreads();

    float val = 0.0f;
    if (t < NN) {
        float w_  = sm->w[t];
        float rm  = DYC * w_ * (sm->part[0][t] + sm->part[1][t]);
        float klr = rm * __logf(rm + 1e-10f) - rm + 1.0f;
        float tp  = w_ * (sm->part[2][t] + sm->part[3][t]) * (DXC * DYC);
        float cm  = DXC * sm->z[t] * sm->csave[t];
        float klc = cm * __logf(cm + 1e-10f) - cm + 1.0f;
        val = klr * DXC + klc * DYC + tp;
    }
    #pragma unroll
    for (int o = 16; o; o >>= 1) val += __shfl_down_sync(0xFFFFFFFFu, val, o);
    if (lane == 0) sm->red[wp] = val;
    __syncthreads();
    if (t == 0) {
        float s = 0.0f;
        #pragma unroll
        for (int i = 0; i < 16; i++) s += sm->red[i];
        out[b] = s;
    }
}

extern "C" void kernel_launch(void* const* d_in, const int* in_sizes, int n_in,
                              void* d_out, int out_size)
{
    const float* D = (const float*)d_in[0];
    float* out = (float*)d_out;
    (void)in_sizes; (void)n_in; (void)out_size;
    size_t smem = sizeof(Smem);
    cudaFuncSetAttribute(wfr_kernel, cudaFuncAttributeMaxDynamicSharedMemorySize, (int)smem);
    wfr_kernel<<<NB, 512, smem>>>(D, out);
}